// round 4
// baseline (speedup 1.0000x reference)
#include <cuda_runtime.h>
#include <math.h>

#define Bsz 4
#define Sq  2048
#define Dm  1024
#define Hn  16
#define HDm 64
#define FFm 2048
#define ROWS (Bsz * Sq)   // 8192

// ---------------- scratch (no allocations allowed) ----------------
__device__ float g_xn[ROWS * Dm];
__device__ float g_q [ROWS * Dm];
__device__ float g_k [ROWS * Dm];
__device__ float g_v [ROWS * Dm];
__device__ float g_ao[ROWS * Dm];
__device__ float g_x1[ROWS * Dm];
__device__ float g_xm[ROWS * Dm];
__device__ float g_h [ROWS * FFm];

// ---------------- LayerNorm ----------------
// one block per row (1024 elems), 256 threads, 4 elems/thread
__global__ void __launch_bounds__(256) ln_kernel(const float* __restrict__ x,
                                                 const float* __restrict__ g,
                                                 const float* __restrict__ b,
                                                 float* __restrict__ out) {
    int row = blockIdx.x;
    const float* xr = x + (size_t)row * Dm;
    int c = threadIdx.x * 4;
    float4 xv = *(const float4*)&xr[c];
    float s  = xv.x + xv.y + xv.z + xv.w;
    float ss = xv.x*xv.x + xv.y*xv.y + xv.z*xv.z + xv.w*xv.w;
    #pragma unroll
    for (int m = 16; m > 0; m >>= 1) {
        s  += __shfl_xor_sync(0xffffffffu, s,  m);
        ss += __shfl_xor_sync(0xffffffffu, ss, m);
    }
    __shared__ float sred[16];
    int w = threadIdx.x >> 5, lane = threadIdx.x & 31;
    if (lane == 0) { sred[w] = s; sred[w + 8] = ss; }
    __syncthreads();
    float tot = 0.f, tot2 = 0.f;
    #pragma unroll
    for (int i = 0; i < 8; i++) { tot += sred[i]; tot2 += sred[8 + i]; }
    float mean = tot * (1.0f / Dm);
    float var  = tot2 * (1.0f / Dm) - mean * mean;
    float rstd = rsqrtf(var + 1e-5f);
    float4 gv = *(const float4*)&g[c];
    float4 bv = *(const float4*)&b[c];
    float4 o;
    o.x = (xv.x - mean) * rstd * gv.x + bv.x;
    o.y = (xv.y - mean) * rstd * gv.y + bv.y;
    o.z = (xv.z - mean) * rstd * gv.z + bv.z;
    o.w = (xv.w - mean) * rstd * gv.w + bv.w;
    *(float4*)&out[(size_t)row * Dm + c] = o;
}

// ---------------- SGEMM: C[M,N] = A[M,K] @ W[N,K]^T (+ bias / residual / gelu) ----------------
// MODE 0: plain   MODE 1: + bias + residual   MODE 2: gelu( . + bias )
#define BM 128
#define BN 128
#define BKg 16
#define TMg 8
#define TNg 8

__device__ __forceinline__ float gelu_exact(float v) {
    return 0.5f * v * (1.0f + erff(v * 0.70710678118654752f));
}

template<int MODE>
__global__ void __launch_bounds__(256) sgemm_kernel(
    const float* __restrict__ A, const float* __restrict__ W,
    const float* __restrict__ bias, const float* __restrict__ res,
    float* __restrict__ C, int M, int N, int K)
{
    __shared__ float As[BKg][BM];
    __shared__ float Bs[BKg][BN];
    int t  = threadIdx.x;
    int tx = t & 15, ty = t >> 4;
    int rowBase = blockIdx.y * BM;
    int colBase = blockIdx.x * BN;

    float acc[TMg][TNg];
    #pragma unroll
    for (int i = 0; i < TMg; i++)
        #pragma unroll
        for (int j = 0; j < TNg; j++) acc[i][j] = 0.f;

    for (int k0 = 0; k0 < K; k0 += BKg) {
        #pragma unroll
        for (int sidx = 0; sidx < 2; sidx++) {
            int vid = t + sidx * 256;       // 0..511
            int r   = vid >> 2;             // 0..127
            int c4  = vid & 3;              // 0..3
            float4 a4 = *(const float4*)&A[(size_t)(rowBase + r) * K + k0 + c4 * 4];
            As[c4*4+0][r] = a4.x; As[c4*4+1][r] = a4.y;
            As[c4*4+2][r] = a4.z; As[c4*4+3][r] = a4.w;
            float4 b4 = *(const float4*)&W[(size_t)(colBase + r) * K + k0 + c4 * 4];
            Bs[c4*4+0][r] = b4.x; Bs[c4*4+1][r] = b4.y;
            Bs[c4*4+2][r] = b4.z; Bs[c4*4+3][r] = b4.w;
        }
        __syncthreads();
        #pragma unroll
        for (int kk = 0; kk < BKg; kk++) {
            float4 a0 = *(const float4*)&As[kk][ty * TMg];
            float4 a1 = *(const float4*)&As[kk][ty * TMg + 4];
            float4 b0 = *(const float4*)&Bs[kk][tx * TNg];
            float4 b1 = *(const float4*)&Bs[kk][tx * TNg + 4];
            float av[TMg] = {a0.x,a0.y,a0.z,a0.w,a1.x,a1.y,a1.z,a1.w};
            float bv[TNg] = {b0.x,b0.y,b0.z,b0.w,b1.x,b1.y,b1.z,b1.w};
            #pragma unroll
            for (int i = 0; i < TMg; i++)
                #pragma unroll
                for (int j = 0; j < TNg; j++)
                    acc[i][j] += av[i] * bv[j];
        }
        __syncthreads();
    }

    #pragma unroll
    for (int i = 0; i < TMg; i++) {
        int row = rowBase + ty * TMg + i;
        #pragma unroll
        for (int j = 0; j < TNg; j += 4) {
            int col = colBase + tx * TNg + j;
            float4 r4;
            r4.x = acc[i][j+0]; r4.y = acc[i][j+1];
            r4.z = acc[i][j+2]; r4.w = acc[i][j+3];
            if (MODE >= 1) {
                float4 bi = *(const float4*)&bias[col];
                r4.x += bi.x; r4.y += bi.y; r4.z += bi.z; r4.w += bi.w;
            }
            if (MODE == 1) {
                float4 rr = *(const float4*)&res[(size_t)row * N + col];
                r4.x += rr.x; r4.y += rr.y; r4.z += rr.z; r4.w += rr.w;
            }
            if (MODE == 2) {
                r4.x = gelu_exact(r4.x); r4.y = gelu_exact(r4.y);
                r4.z = gelu_exact(r4.z); r4.w = gelu_exact(r4.w);
            }
            *(float4*)&C[(size_t)row * N + col] = r4;
        }
    }
}

// ---------------- Flash attention ----------------
// grid (S/64, B*H), 256 threads. q-tile 64 rows, stream K/V in 64-row tiles.
// smem: Qs[64][76], KPs[64][76] (K tile, then reused for P), Vs[64][76], Ms[64]
#define QS 76
#define ATTN_SMEM ((3 * 64 * QS + 64) * (int)sizeof(float))

__global__ void __launch_bounds__(256) attn_kernel(
    const float* __restrict__ q, const float* __restrict__ k,
    const float* __restrict__ v, const float* __restrict__ pm,
    float* __restrict__ out)
{
    extern __shared__ float sm[];
    float* Qs  = sm;
    float* KPs = Qs + 64 * QS;
    float* Vs  = KPs + 64 * QS;
    float* Ms  = Vs + 64 * QS;

    int t  = threadIdx.x;
    int tx = t & 15, ty = t >> 4;
    int qtile = blockIdx.x;           // 0..31
    int bh = blockIdx.y;              // 0..63
    int b  = bh >> 4, h = bh & 15;
    int q0 = qtile * 64;

    const float* qb = q + ((size_t)b * Sq) * Dm + h * HDm;
    const float* kb = k + ((size_t)b * Sq) * Dm + h * HDm;
    const float* vb = v + ((size_t)b * Sq) * Dm + h * HDm;

    // load Q tile (64 rows x 64 cols = 1024 float4)
    for (int i = t; i < 1024; i += 256) {
        int r = i >> 4, c4 = i & 15;
        float4 f = *(const float4*)&qb[(size_t)(q0 + r) * Dm + c4 * 4];
        *(float4*)&Qs[r * QS + c4 * 4] = f;
    }

    float mrow[4], lrow[4], O[4][4];
    #pragma unroll
    for (int i = 0; i < 4; i++) {
        mrow[i] = -1e30f; lrow[i] = 0.f;
        #pragma unroll
        for (int j = 0; j < 4; j++) O[i][j] = 0.f;
    }

    for (int kt = 0; kt < Sq / 64; kt++) {
        int k0 = kt * 64;
        // load K, V tiles + mask
        for (int i = t; i < 1024; i += 256) {
            int r = i >> 4, c4 = i & 15;
            *(float4*)&KPs[r * QS + c4 * 4] =
                *(const float4*)&kb[(size_t)(k0 + r) * Dm + c4 * 4];
            *(float4*)&Vs[r * QS + c4 * 4] =
                *(const float4*)&vb[(size_t)(k0 + r) * Dm + c4 * 4];
        }
        if (t < 64) Ms[t] = (1.0f - pm[b * Sq + k0 + t]) * -10000.0f;
        __syncthreads();

        // scores: s[i][j] = Q[ty*4+i] . K[tx*4+j]
        float s4[4][4];
        #pragma unroll
        for (int i = 0; i < 4; i++)
            #pragma unroll
            for (int j = 0; j < 4; j++) s4[i][j] = 0.f;
        #pragma unroll 4
        for (int kk = 0; kk < 64; kk += 4) {
            float4 qf[4], kf[4];
            #pragma unroll
            for (int i = 0; i < 4; i++) qf[i] = *(const float4*)&Qs[(ty*4+i)*QS + kk];
            #pragma unroll
            for (int j = 0; j < 4; j++) kf[j] = *(const float4*)&KPs[(tx*4+j)*QS + kk];
            #pragma unroll
            for (int i = 0; i < 4; i++)
                #pragma unroll
                for (int j = 0; j < 4; j++)
                    s4[i][j] += qf[i].x*kf[j].x + qf[i].y*kf[j].y
                              + qf[i].z*kf[j].z + qf[i].w*kf[j].w;
        }
        #pragma unroll
        for (int i = 0; i < 4; i++)
            #pragma unroll
            for (int j = 0; j < 4; j++)
                s4[i][j] = s4[i][j] * 0.125f + Ms[tx*4+j];

        // online softmax
        float p4[4][4], rsum[4];
        #pragma unroll
        for (int i = 0; i < 4; i++) {
            float rmax = fmaxf(fmaxf(s4[i][0], s4[i][1]), fmaxf(s4[i][2], s4[i][3]));
            #pragma unroll
            for (int m = 1; m < 16; m <<= 1)
                rmax = fmaxf(rmax, __shfl_xor_sync(0xffffffffu, rmax, m));
            float mnew = fmaxf(mrow[i], rmax);
            float alpha = expf(mrow[i] - mnew);
            float rs = 0.f;
            #pragma unroll
            for (int j = 0; j < 4; j++) {
                p4[i][j] = expf(s4[i][j] - mnew);
                rs += p4[i][j];
            }
            #pragma unroll
            for (int m = 1; m < 16; m <<= 1)
                rs += __shfl_xor_sync(0xffffffffu, rs, m);
            lrow[i] = lrow[i] * alpha + rs;
            mrow[i] = mnew;
            #pragma unroll
            for (int j = 0; j < 4; j++) O[i][j] *= alpha;
            rsum[i] = rs; (void)rsum[i];
        }
        __syncthreads();  // done reading K tile
        #pragma unroll
        for (int i = 0; i < 4; i++)
            #pragma unroll
            for (int j = 0; j < 4; j++)
                KPs[(ty*4+i)*QS + tx*4+j] = p4[i][j];
        __syncthreads();

        // O += P @ V
        #pragma unroll 4
        for (int kk = 0; kk < 64; kk++) {
            float pf[4];
            #pragma unroll
            for (int i = 0; i < 4; i++) pf[i] = KPs[(ty*4+i)*QS + kk];
            float4 vf = *(const float4*)&Vs[kk*QS + tx*4];
            #pragma unroll
            for (int i = 0; i < 4; i++) {
                O[i][0] += pf[i] * vf.x;
                O[i][1] += pf[i] * vf.y;
                O[i][2] += pf[i] * vf.z;
                O[i][3] += pf[i] * vf.w;
            }
        }
        __syncthreads();  // before next tile overwrites K/V
    }

    float* ob = out + ((size_t)b * Sq + q0) * Dm + h * HDm;
    #pragma unroll
    for (int i = 0; i < 4; i++) {
        float inv = 1.0f / lrow[i];
        int r = ty * 4 + i;
        float4 o;
        o.x = O[i][0] * inv; o.y = O[i][1] * inv;
        o.z = O[i][2] * inv; o.w = O[i][3] * inv;
        *(float4*)&ob[(size_t)r * Dm + tx * 4] = o;
    }
}

// ---------------- launch ----------------
extern "C" void kernel_launch(void* const* d_in, const int* in_sizes, int n_in,
                              void* d_out, int out_size) {
    const float* x     = (const float*)d_in[0];
    const float* pmask = (const float*)d_in[1];
    const float* Wq    = (const float*)d_in[2];
    const float* Wk    = (const float*)d_in[3];
    const float* Wv    = (const float*)d_in[4];
    const float* Wu    = (const float*)d_in[5];
    const float* bu    = (const float*)d_in[6];
    const float* W1    = (const float*)d_in[7];
    const float* b1    = (const float*)d_in[8];
    const float* W2    = (const float*)d_in[9];
    const float* b2    = (const float*)d_in[10];
    const float* g1    = (const float*)d_in[11];
    const float* be1   = (const float*)d_in[12];
    const float* g2    = (const float*)d_in[13];
    const float* be2   = (const float*)d_in[14];
    float* out = (float*)d_out;

    float *xn, *qb, *kb, *vb, *ao, *x1, *xm, *hb;
    cudaGetSymbolAddress((void**)&xn, g_xn);
    cudaGetSymbolAddress((void**)&qb, g_q);
    cudaGetSymbolAddress((void**)&kb, g_k);
    cudaGetSymbolAddress((void**)&vb, g_v);
    cudaGetSymbolAddress((void**)&ao, g_ao);
    cudaGetSymbolAddress((void**)&x1, g_x1);
    cudaGetSymbolAddress((void**)&xm, g_xm);
    cudaGetSymbolAddress((void**)&hb, g_h);

    cudaFuncSetAttribute(attn_kernel, cudaFuncAttributeMaxDynamicSharedMemorySize,
                         ATTN_SMEM);

    dim3 gD(Dm / BN, ROWS / BM);     // (8, 64)
    dim3 gF(FFm / BN, ROWS / BM);    // (16, 64)

    ln_kernel<<<ROWS, 256>>>(x, g1, be1, xn);

    sgemm_kernel<0><<<gD, 256>>>(xn, Wq, nullptr, nullptr, qb, ROWS, Dm, Dm);
    sgemm_kernel<0><<<gD, 256>>>(xn, Wk, nullptr, nullptr, kb, ROWS, Dm, Dm);
    sgemm_kernel<0><<<gD, 256>>>(xn, Wv, nullptr, nullptr, vb, ROWS, Dm, Dm);

    attn_kernel<<<dim3(Sq / 64, Bsz * Hn), 256, ATTN_SMEM>>>(qb, kb, vb, pmask, ao);

    sgemm_kernel<1><<<gD, 256>>>(ao, Wu, bu, x, x1, ROWS, Dm, Dm);

    ln_kernel<<<ROWS, 256>>>(x1, g2, be2, xm);

    sgemm_kernel<2><<<gF, 256>>>(xm, W1, b1, nullptr, hb, ROWS, FFm, Dm);

    sgemm_kernel<1><<<gD, 256>>>(hb, W2, b2, x1, out, ROWS, Dm, FFm);
}

// round 6
// speedup vs baseline: 1.8709x; 1.8709x over previous
#include <cuda_runtime.h>
#include <cuda_fp16.h>
#include <math.h>
#include <stdint.h>

#define Bsz 4
#define Sq  2048
#define Dm  1024
#define Hn  16
#define HDm 64
#define FFm 2048
#define ROWS (Bsz * Sq)   // 8192

// ---------------- scratch (no allocations allowed) ----------------
__device__ __half g_xn16[ROWS * Dm];
__device__ float  g_q [ROWS * Dm];
__device__ float  g_k [ROWS * Dm];
__device__ float  g_v [ROWS * Dm];
__device__ __half g_ao16[ROWS * Dm];
__device__ float  g_x1[ROWS * Dm];
__device__ __half g_xm16[ROWS * Dm];
__device__ __half g_h16[ROWS * FFm];
__device__ __half g_wq16[Dm * Dm];
__device__ __half g_wk16[Dm * Dm];
__device__ __half g_wv16[Dm * Dm];
__device__ __half g_wu16[Dm * Dm];
__device__ __half g_w116[FFm * Dm];
__device__ __half g_w216[Dm * FFm];

// ---------------- PTX helpers (sm_80-portable only!) ----------------
__device__ __forceinline__ uint32_t smem_u32(const void* p) {
    uint32_t a;
    asm("{ .reg .u64 t; cvta.to.shared.u64 t, %1; cvt.u32.u64 %0, t; }"
        : "=r"(a) : "l"(p));
    return a;
}
__device__ __forceinline__ void cp16(uint32_t saddr, const void* gaddr) {
    asm volatile("cp.async.cg.shared.global [%0], [%1], 16;"
                 :: "r"(saddr), "l"(gaddr));
}
#define CP_COMMIT() asm volatile("cp.async.commit_group;" ::: "memory")
#define CP_WAIT1()  asm volatile("cp.async.wait_group 1;" ::: "memory")
#define SWZ(o) ((o) ^ (((o) >> 3) & 0x70))

__device__ __forceinline__ void ldsm4(uint32_t* r, uint32_t addr) {
    asm volatile("ldmatrix.sync.aligned.m8n8.x4.shared.b16 {%0,%1,%2,%3}, [%4];"
                 : "=r"(r[0]), "=r"(r[1]), "=r"(r[2]), "=r"(r[3]) : "r"(addr));
}
__device__ __forceinline__ void mma16816(float* c, const uint32_t* a,
                                         const uint32_t* b) {
    asm volatile("mma.sync.aligned.m16n8k16.row.col.f32.f16.f16.f32 "
                 "{%0,%1,%2,%3}, {%4,%5,%6,%7}, {%8,%9}, {%0,%1,%2,%3};"
                 : "+f"(c[0]), "+f"(c[1]), "+f"(c[2]), "+f"(c[3])
                 : "r"(a[0]), "r"(a[1]), "r"(a[2]), "r"(a[3]),
                   "r"(b[0]), "r"(b[1]));
}

// ---------------- fp32 -> fp16 convert ----------------
__global__ void __launch_bounds__(256) f2h_kernel(const float* __restrict__ in,
                                                  __half* __restrict__ out, int n) {
    int i = (blockIdx.x * 256 + threadIdx.x) * 4;
    if (i < n) {
        float4 v = *(const float4*)&in[i];
        *(__half2*)&out[i]     = __floats2half2_rn(v.x, v.y);
        *(__half2*)&out[i + 2] = __floats2half2_rn(v.z, v.w);
    }
}

// ---------------- LayerNorm (fp32 in, fp16 out) ----------------
__global__ void __launch_bounds__(256) ln_kernel(const float* __restrict__ x,
                                                 const float* __restrict__ g,
                                                 const float* __restrict__ b,
                                                 __half* __restrict__ out) {
    int row = blockIdx.x;
    const float* xr = x + (size_t)row * Dm;
    int c = threadIdx.x * 4;
    float4 xv = *(const float4*)&xr[c];
    float s  = xv.x + xv.y + xv.z + xv.w;
    float ss = xv.x*xv.x + xv.y*xv.y + xv.z*xv.z + xv.w*xv.w;
    #pragma unroll
    for (int m = 16; m > 0; m >>= 1) {
        s  += __shfl_xor_sync(0xffffffffu, s,  m);
        ss += __shfl_xor_sync(0xffffffffu, ss, m);
    }
    __shared__ float sred[16];
    int w = threadIdx.x >> 5, lane = threadIdx.x & 31;
    if (lane == 0) { sred[w] = s; sred[w + 8] = ss; }
    __syncthreads();
    float tot = 0.f, tot2 = 0.f;
    #pragma unroll
    for (int i = 0; i < 8; i++) { tot += sred[i]; tot2 += sred[8 + i]; }
    float mean = tot * (1.0f / Dm);
    float var  = tot2 * (1.0f / Dm) - mean * mean;
    float rstd = rsqrtf(var + 1e-5f);
    float4 gv = *(const float4*)&g[c];
    float4 bv = *(const float4*)&b[c];
    float o0 = (xv.x - mean) * rstd * gv.x + bv.x;
    float o1 = (xv.y - mean) * rstd * gv.y + bv.y;
    float o2 = (xv.z - mean) * rstd * gv.z + bv.z;
    float o3 = (xv.w - mean) * rstd * gv.w + bv.w;
    __half* orow = out + (size_t)row * Dm + c;
    *(__half2*)&orow[0] = __floats2half2_rn(o0, o1);
    *(__half2*)&orow[2] = __floats2half2_rn(o2, o3);
}

// ---------------- HMMA fp16 GEMM: C[M,N] = A[M,K] @ W[N,K]^T ----------------
// MODE 0: plain (float out)  MODE 1: +bias+residual (float out)
// MODE 2: gelu(.+bias) (half out)
// CTA tile 128x128x64, 3-stage cp.async pipeline, 8 warps (2x4), warp 64x32.
#define NST 3
#define STAGE_BYTES 32768              // As 16KB + Bs 16KB (128 rows x 128B, SW128)
#define GSMEM (1024 + NST * STAGE_BYTES)

__device__ __forceinline__ float gelu_exact(float v) {
    return 0.5f * v * (1.0f + erff(v * 0.70710678118654752f));
}

template<int MODE, typename TOUT>
__global__ void __launch_bounds__(256, 2)
hgemm_mma(const __half* __restrict__ A, const __half* __restrict__ W,
          const float* __restrict__ bias, const float* __restrict__ resid,
          TOUT* __restrict__ C, int M, int N, int K)
{
    extern __shared__ char dsm[];
    uint32_t stage0 = (smem_u32(dsm) + 1023) & ~1023u;

    int tid  = threadIdx.x;
    int wid  = tid >> 5, lane = tid & 31;
    int wm   = wid & 1;            // 0..1 : 64-row group
    int wn   = wid >> 1;           // 0..3 : 32-col group
    int rowBase = blockIdx.y * 128;
    int colBase = blockIdx.x * 128;
    int nchunk = K >> 6;           // 64 fp16 per chunk (128B rows)

    float acc[4][4][4];
    #pragma unroll
    for (int i = 0; i < 4; i++)
        #pragma unroll
        for (int j = 0; j < 4; j++)
            #pragma unroll
            for (int e = 0; e < 4; e++) acc[i][j][e] = 0.f;

    auto fill = [&](int chunk, int stage) {
        uint32_t sA = stage0 + stage * STAGE_BYTES;
        uint32_t sB = sA + 16384;
        const __half* Ab = A + (size_t)rowBase * K + chunk * 64;
        const __half* Wb = W + (size_t)colBase * K + chunk * 64;
        #pragma unroll
        for (int it = 0; it < 8; it++) {
            int idx = it * 256 + tid;       // 0..2047
            int half = idx >> 10;           // 0: A, 1: B
            int sub  = idx & 1023;
            int r = sub >> 3, c = sub & 7;  // row 0..127, 16B col 0..7
            uint32_t off = SWZ(r * 128 + c * 16);
            if (half == 0) cp16(sA + off, Ab + (size_t)r * K + c * 8);
            else           cp16(sB + off, Wb + (size_t)r * K + c * 8);
        }
        CP_COMMIT();
    };

    fill(0, 0);
    fill(1, 1);

    // ldmatrix lane-address components (constant per thread)
    int a_row_off = lane & 15;              // row within 16
    int a_k_off   = (lane >> 4) << 4;       // 0 or 16 bytes (k halves)
    int b_row_off = (lane & 7) + ((lane >> 4) << 3);  // n within 16
    int b_k_off   = ((lane >> 3) & 1) << 4; // 0 or 16 bytes

    for (int i = 0; i < nchunk; i++) {
        CP_WAIT1();
        __syncthreads();
        if (i + 2 < nchunk) fill(i + 2, (i + 2) % NST);

        uint32_t sA = stage0 + (i % NST) * STAGE_BYTES;
        uint32_t sB = sA + 16384;
        #pragma unroll
        for (int ks = 0; ks < 4; ks++) {
            int kb = ks * 32;               // 16 fp16 = 32 bytes per k-step
            uint32_t af[4][4], bf[2][4];
            #pragma unroll
            for (int m = 0; m < 4; m++) {
                int row = wm * 64 + m * 16 + a_row_off;
                ldsm4(af[m], sA + SWZ(row * 128 + kb + a_k_off));
            }
            #pragma unroll
            for (int j = 0; j < 2; j++) {
                int row = wn * 32 + j * 16 + b_row_off;
                ldsm4(bf[j], sB + SWZ(row * 128 + kb + b_k_off));
            }
            #pragma unroll
            for (int m = 0; m < 4; m++)
                #pragma unroll
                for (int n = 0; n < 4; n++)
                    mma16816(acc[m][n], af[m], &bf[n >> 1][(n & 1) * 2]);
        }
        __syncthreads();
    }

    // epilogue: registers -> global, fused bias/residual/gelu
    int r0 = rowBase + wm * 64 + (lane >> 2);
    int c0 = colBase + wn * 32 + (lane & 3) * 2;
    #pragma unroll
    for (int m = 0; m < 4; m++) {
        #pragma unroll
        for (int n = 0; n < 4; n++) {
            int col = c0 + n * 8;
            float2 bi = make_float2(0.f, 0.f);
            if (MODE >= 1) bi = *(const float2*)&bias[col];
            #pragma unroll
            for (int hrow = 0; hrow < 2; hrow++) {
                int row = r0 + m * 16 + hrow * 8;
                float v0 = acc[m][n][hrow * 2 + 0];
                float v1 = acc[m][n][hrow * 2 + 1];
                if (MODE >= 1) { v0 += bi.x; v1 += bi.y; }
                if (MODE == 1) {
                    float2 rr = *(const float2*)&resid[(size_t)row * N + col];
                    v0 += rr.x; v1 += rr.y;
                }
                if (MODE == 2) { v0 = gelu_exact(v0); v1 = gelu_exact(v1); }
                if (sizeof(TOUT) == 2) {
                    *(__half2*)((__half*)C + (size_t)row * N + col) =
                        __floats2half2_rn(v0, v1);
                } else {
                    *(float2*)((float*)C + (size_t)row * N + col) =
                        make_float2(v0, v1);
                }
            }
        }
    }
}

// ---------------- Flash attention (fp32 compute, fp16 output) ----------------
#define QS 76
#define ATTN_SMEM ((3 * 64 * QS + 64) * (int)sizeof(float))

__global__ void __launch_bounds__(256) attn_kernel(
    const float* __restrict__ q, const float* __restrict__ k,
    const float* __restrict__ v, const float* __restrict__ pm,
    __half* __restrict__ out)
{
    extern __shared__ float sm[];
    float* Qs  = sm;
    float* KPs = Qs + 64 * QS;
    float* Vs  = KPs + 64 * QS;
    float* Ms  = Vs + 64 * QS;

    int t  = threadIdx.x;
    int tx = t & 15, ty = t >> 4;
    int qtile = blockIdx.x;
    int bh = blockIdx.y;
    int b  = bh >> 4, h = bh & 15;
    int q0 = qtile * 64;

    const float* qb = q + ((size_t)b * Sq) * Dm + h * HDm;
    const float* kb = k + ((size_t)b * Sq) * Dm + h * HDm;
    const float* vb = v + ((size_t)b * Sq) * Dm + h * HDm;

    for (int i = t; i < 1024; i += 256) {
        int r = i >> 4, c4 = i & 15;
        *(float4*)&Qs[r * QS + c4 * 4] =
            *(const float4*)&qb[(size_t)(q0 + r) * Dm + c4 * 4];
    }

    float mrow[4], lrow[4], O[4][4];
    #pragma unroll
    for (int i = 0; i < 4; i++) {
        mrow[i] = -1e30f; lrow[i] = 0.f;
        #pragma unroll
        for (int j = 0; j < 4; j++) O[i][j] = 0.f;
    }

    for (int kt = 0; kt < Sq / 64; kt++) {
        int k0 = kt * 64;
        for (int i = t; i < 1024; i += 256) {
            int r = i >> 4, c4 = i & 15;
            *(float4*)&KPs[r * QS + c4 * 4] =
                *(const float4*)&kb[(size_t)(k0 + r) * Dm + c4 * 4];
            *(float4*)&Vs[r * QS + c4 * 4] =
                *(const float4*)&vb[(size_t)(k0 + r) * Dm + c4 * 4];
        }
        if (t < 64) Ms[t] = (1.0f - pm[b * Sq + k0 + t]) * -10000.0f;
        __syncthreads();

        float s4[4][4];
        #pragma unroll
        for (int i = 0; i < 4; i++)
            #pragma unroll
            for (int j = 0; j < 4; j++) s4[i][j] = 0.f;
        #pragma unroll 4
        for (int kk = 0; kk < 64; kk += 4) {
            float4 qf[4], kf[4];
            #pragma unroll
            for (int i = 0; i < 4; i++) qf[i] = *(const float4*)&Qs[(ty*4+i)*QS + kk];
            #pragma unroll
            for (int j = 0; j < 4; j++) kf[j] = *(const float4*)&KPs[(tx*4+j)*QS + kk];
            #pragma unroll
            for (int i = 0; i < 4; i++)
                #pragma unroll
                for (int j = 0; j < 4; j++)
                    s4[i][j] += qf[i].x*kf[j].x + qf[i].y*kf[j].y
                              + qf[i].z*kf[j].z + qf[i].w*kf[j].w;
        }
        #pragma unroll
        for (int i = 0; i < 4; i++)
            #pragma unroll
            for (int j = 0; j < 4; j++)
                s4[i][j] = s4[i][j] * 0.125f + Ms[tx*4+j];

        float p4[4][4];
        #pragma unroll
        for (int i = 0; i < 4; i++) {
            float rmax = fmaxf(fmaxf(s4[i][0], s4[i][1]), fmaxf(s4[i][2], s4[i][3]));
            #pragma unroll
            for (int m = 1; m < 16; m <<= 1)
                rmax = fmaxf(rmax, __shfl_xor_sync(0xffffffffu, rmax, m));
            float mnew = fmaxf(mrow[i], rmax);
            float alpha = expf(mrow[i] - mnew);
            float rs = 0.f;
            #pragma unroll
            for (int j = 0; j < 4; j++) {
                p4[i][j] = expf(s4[i][j] - mnew);
                rs += p4[i][j];
            }
            #pragma unroll
            for (int m = 1; m < 16; m <<= 1)
                rs += __shfl_xor_sync(0xffffffffu, rs, m);
            lrow[i] = lrow[i] * alpha + rs;
            mrow[i] = mnew;
            #pragma unroll
            for (int j = 0; j < 4; j++) O[i][j] *= alpha;
        }
        __syncthreads();
        #pragma unroll
        for (int i = 0; i < 4; i++)
            #pragma unroll
            for (int j = 0; j < 4; j++)
                KPs[(ty*4+i)*QS + tx*4+j] = p4[i][j];
        __syncthreads();

        #pragma unroll 4
        for (int kk = 0; kk < 64; kk++) {
            float pf[4];
            #pragma unroll
            for (int i = 0; i < 4; i++) pf[i] = KPs[(ty*4+i)*QS + kk];
            float4 vf = *(const float4*)&Vs[kk*QS + tx*4];
            #pragma unroll
            for (int i = 0; i < 4; i++) {
                O[i][0] += pf[i] * vf.x;
                O[i][1] += pf[i] * vf.y;
                O[i][2] += pf[i] * vf.z;
                O[i][3] += pf[i] * vf.w;
            }
        }
        __syncthreads();
    }

    __half* ob = out + ((size_t)b * Sq + q0) * Dm + h * HDm;
    #pragma unroll
    for (int i = 0; i < 4; i++) {
        float inv = 1.0f / lrow[i];
        int r = ty * 4 + i;
        __half* op = ob + (size_t)r * Dm + tx * 4;
        *(__half2*)&op[0] = __floats2half2_rn(O[i][0] * inv, O[i][1] * inv);
        *(__half2*)&op[2] = __floats2half2_rn(O[i][2] * inv, O[i][3] * inv);
    }
}

// ---------------- launch ----------------
extern "C" void kernel_launch(void* const* d_in, const int* in_sizes, int n_in,
                              void* d_out, int out_size) {
    const float* x     = (const float*)d_in[0];
    const float* pmask = (const float*)d_in[1];
    const float* Wq    = (const float*)d_in[2];
    const float* Wk    = (const float*)d_in[3];
    const float* Wv    = (const float*)d_in[4];
    const float* Wu    = (const float*)d_in[5];
    const float* bu    = (const float*)d_in[6];
    const float* W1    = (const float*)d_in[7];
    const float* b1    = (const float*)d_in[8];
    const float* W2    = (const float*)d_in[9];
    const float* b2    = (const float*)d_in[10];
    const float* g1    = (const float*)d_in[11];
    const float* be1   = (const float*)d_in[12];
    const float* g2    = (const float*)d_in[13];
    const float* be2   = (const float*)d_in[14];
    float* out = (float*)d_out;

    __half *xn16, *ao16, *xm16, *h16, *wq16, *wk16, *wv16, *wu16, *w116, *w216;
    float *qb, *kb, *vb, *x1;
    cudaGetSymbolAddress((void**)&xn16, g_xn16);
    cudaGetSymbolAddress((void**)&qb,   g_q);
    cudaGetSymbolAddress((void**)&kb,   g_k);
    cudaGetSymbolAddress((void**)&vb,   g_v);
    cudaGetSymbolAddress((void**)&ao16, g_ao16);
    cudaGetSymbolAddress((void**)&x1,   g_x1);
    cudaGetSymbolAddress((void**)&xm16, g_xm16);
    cudaGetSymbolAddress((void**)&h16,  g_h16);
    cudaGetSymbolAddress((void**)&wq16, g_wq16);
    cudaGetSymbolAddress((void**)&wk16, g_wk16);
    cudaGetSymbolAddress((void**)&wv16, g_wv16);
    cudaGetSymbolAddress((void**)&wu16, g_wu16);
    cudaGetSymbolAddress((void**)&w116, g_w116);
    cudaGetSymbolAddress((void**)&w216, g_w216);

    cudaFuncSetAttribute(attn_kernel, cudaFuncAttributeMaxDynamicSharedMemorySize,
                         ATTN_SMEM);
    cudaFuncSetAttribute(hgemm_mma<0, float>,
                         cudaFuncAttributeMaxDynamicSharedMemorySize, GSMEM);
    cudaFuncSetAttribute(hgemm_mma<1, float>,
                         cudaFuncAttributeMaxDynamicSharedMemorySize, GSMEM);
    cudaFuncSetAttribute(hgemm_mma<2, __half>,
                         cudaFuncAttributeMaxDynamicSharedMemorySize, GSMEM);

    // weight conversions
    f2h_kernel<<<Dm * Dm / 1024, 256>>>(Wq, wq16, Dm * Dm);
    f2h_kernel<<<Dm * Dm / 1024, 256>>>(Wk, wk16, Dm * Dm);
    f2h_kernel<<<Dm * Dm / 1024, 256>>>(Wv, wv16, Dm * Dm);
    f2h_kernel<<<Dm * Dm / 1024, 256>>>(Wu, wu16, Dm * Dm);
    f2h_kernel<<<FFm * Dm / 1024, 256>>>(W1, w116, FFm * Dm);
    f2h_kernel<<<Dm * FFm / 1024, 256>>>(W2, w216, Dm * FFm);

    dim3 gD(Dm / 128, ROWS / 128);    // (8, 64)
    dim3 gF(FFm / 128, ROWS / 128);   // (16, 64)

    ln_kernel<<<ROWS, 256>>>(x, g1, be1, xn16);

    hgemm_mma<0, float><<<gD, 256, GSMEM>>>(xn16, wq16, nullptr, nullptr, qb, ROWS, Dm, Dm);
    hgemm_mma<0, float><<<gD, 256, GSMEM>>>(xn16, wk16, nullptr, nullptr, kb, ROWS, Dm, Dm);
    hgemm_mma<0, float><<<gD, 256, GSMEM>>>(xn16, wv16, nullptr, nullptr, vb, ROWS, Dm, Dm);

    attn_kernel<<<dim3(Sq / 64, Bsz * Hn), 256, ATTN_SMEM>>>(qb, kb, vb, pmask, ao16);

    hgemm_mma<1, float><<<gD, 256, GSMEM>>>(ao16, wu16, bu, x, x1, ROWS, Dm, Dm);

    ln_kernel<<<ROWS, 256>>>(x1, g2, be2, xm16);

    hgemm_mma<2, __half><<<gF, 256, GSMEM>>>(xm16, w116, b1, nullptr, h16, ROWS, FFm, Dm);

    hgemm_mma<1, float><<<gD, 256, GSMEM>>>(h16, w216, b2, x1, out, ROWS, Dm, FFm);
}

// round 7
// speedup vs baseline: 8.5235x; 4.5559x over previous
#include <cuda_runtime.h>
#include <cuda_fp16.h>
#include <math.h>
#include <stdint.h>

#define Bsz 4
#define Sq  2048
#define Dm  1024
#define Hn  16
#define HDm 64
#define FFm 2048
#define ROWS (Bsz * Sq)   // 8192

// ---------------- scratch (no allocations allowed) ----------------
__device__ __half g_xn16[ROWS * Dm];
__device__ __half g_q16[ROWS * Dm];
__device__ __half g_k16[ROWS * Dm];
__device__ __half g_v16[ROWS * Dm];
__device__ __half g_ao16[ROWS * Dm];
__device__ float  g_x1[ROWS * Dm];
__device__ __half g_xm16[ROWS * Dm];
__device__ __half g_h16[ROWS * FFm];
__device__ __half g_wq16[Dm * Dm];
__device__ __half g_wk16[Dm * Dm];
__device__ __half g_wv16[Dm * Dm];
__device__ __half g_wu16[Dm * Dm];
__device__ __half g_w116[FFm * Dm];
__device__ __half g_w216[Dm * FFm];

// ---------------- PTX helpers (sm_80-portable only!) ----------------
__device__ __forceinline__ uint32_t smem_u32(const void* p) {
    uint32_t a;
    asm("{ .reg .u64 t; cvta.to.shared.u64 t, %1; cvt.u32.u64 %0, t; }"
        : "=r"(a) : "l"(p));
    return a;
}
__device__ __forceinline__ void cp16(uint32_t saddr, const void* gaddr) {
    asm volatile("cp.async.cg.shared.global [%0], [%1], 16;"
                 :: "r"(saddr), "l"(gaddr));
}
#define CP_COMMIT() asm volatile("cp.async.commit_group;" ::: "memory")
#define CP_WAIT1()  asm volatile("cp.async.wait_group 1;" ::: "memory")
#define CP_WAIT0()  asm volatile("cp.async.wait_group 0;" ::: "memory")
#define SWZ(o) ((o) ^ (((o) >> 3) & 0x70))

__device__ __forceinline__ void ldsm4(uint32_t* r, uint32_t addr) {
    asm volatile("ldmatrix.sync.aligned.m8n8.x4.shared.b16 {%0,%1,%2,%3}, [%4];"
                 : "=r"(r[0]), "=r"(r[1]), "=r"(r[2]), "=r"(r[3]) : "r"(addr));
}
__device__ __forceinline__ void ldsm4t(uint32_t* r, uint32_t addr) {
    asm volatile("ldmatrix.sync.aligned.m8n8.x4.trans.shared.b16 {%0,%1,%2,%3}, [%4];"
                 : "=r"(r[0]), "=r"(r[1]), "=r"(r[2]), "=r"(r[3]) : "r"(addr));
}
__device__ __forceinline__ void mma16816(float* c, const uint32_t* a,
                                         const uint32_t* b) {
    asm volatile("mma.sync.aligned.m16n8k16.row.col.f32.f16.f16.f32 "
                 "{%0,%1,%2,%3}, {%4,%5,%6,%7}, {%8,%9}, {%0,%1,%2,%3};"
                 : "+f"(c[0]), "+f"(c[1]), "+f"(c[2]), "+f"(c[3])
                 : "r"(a[0]), "r"(a[1]), "r"(a[2]), "r"(a[3]),
                   "r"(b[0]), "r"(b[1]));
}

// fast 2^y on FMA/ALU pipes (y <= 0 expected; clamped). rel err ~1e-6.
#define L2E 1.4426950408889634f
__device__ __forceinline__ float fexp2n(float y) {
    y = fmaxf(y, -125.f);
    float t = y + 12582912.f;               // 1.5 * 2^23 rounding trick
    int n = __float_as_int(t) - 0x4B400000;
    float f = y - (t - 12582912.f);         // f in [-0.5, 0.5]
    float p = 1.f + f * (0.693147182f + f * (0.240226507f + f * (0.0555041087f
              + f * (0.00961812911f + f * 0.00133335581f))));
    return __int_as_float(__float_as_int(p) + (n << 23));
}

// ---------------- fp32 -> fp16 convert ----------------
__global__ void __launch_bounds__(256) f2h_kernel(const float* __restrict__ in,
                                                  __half* __restrict__ out, int n) {
    int i = (blockIdx.x * 256 + threadIdx.x) * 4;
    if (i < n) {
        float4 v = *(const float4*)&in[i];
        *(__half2*)&out[i]     = __floats2half2_rn(v.x, v.y);
        *(__half2*)&out[i + 2] = __floats2half2_rn(v.z, v.w);
    }
}

// ---------------- LayerNorm (fp32 in, fp16 out) ----------------
__global__ void __launch_bounds__(256) ln_kernel(const float* __restrict__ x,
                                                 const float* __restrict__ g,
                                                 const float* __restrict__ b,
                                                 __half* __restrict__ out) {
    int row = blockIdx.x;
    const float* xr = x + (size_t)row * Dm;
    int c = threadIdx.x * 4;
    float4 xv = *(const float4*)&xr[c];
    float s  = xv.x + xv.y + xv.z + xv.w;
    float ss = xv.x*xv.x + xv.y*xv.y + xv.z*xv.z + xv.w*xv.w;
    #pragma unroll
    for (int m = 16; m > 0; m >>= 1) {
        s  += __shfl_xor_sync(0xffffffffu, s,  m);
        ss += __shfl_xor_sync(0xffffffffu, ss, m);
    }
    __shared__ float sred[16];
    int w = threadIdx.x >> 5, lane = threadIdx.x & 31;
    if (lane == 0) { sred[w] = s; sred[w + 8] = ss; }
    __syncthreads();
    float tot = 0.f, tot2 = 0.f;
    #pragma unroll
    for (int i = 0; i < 8; i++) { tot += sred[i]; tot2 += sred[8 + i]; }
    float mean = tot * (1.0f / Dm);
    float var  = tot2 * (1.0f / Dm) - mean * mean;
    float rstd = rsqrtf(var + 1e-5f);
    float4 gv = *(const float4*)&g[c];
    float4 bv = *(const float4*)&b[c];
    float o0 = (xv.x - mean) * rstd * gv.x + bv.x;
    float o1 = (xv.y - mean) * rstd * gv.y + bv.y;
    float o2 = (xv.z - mean) * rstd * gv.z + bv.z;
    float o3 = (xv.w - mean) * rstd * gv.w + bv.w;
    __half* orow = out + (size_t)row * Dm + c;
    *(__half2*)&orow[0] = __floats2half2_rn(o0, o1);
    *(__half2*)&orow[2] = __floats2half2_rn(o2, o3);
}

// ---------------- HMMA fp16 GEMM: C[M,N] = A[M,K] @ W[N,K]^T ----------------
#define NST 3
#define STAGE_BYTES 32768
#define GSMEM (1024 + NST * STAGE_BYTES)

__device__ __forceinline__ float gelu_exact(float v) {
    return 0.5f * v * (1.0f + erff(v * 0.70710678118654752f));
}

template<int MODE, typename TOUT>
__global__ void __launch_bounds__(256, 2)
hgemm_mma(const __half* __restrict__ A, const __half* __restrict__ W,
          const float* __restrict__ bias, const float* __restrict__ resid,
          TOUT* __restrict__ C, int M, int N, int K)
{
    extern __shared__ char dsm[];
    uint32_t stage0 = (smem_u32(dsm) + 1023) & ~1023u;

    int tid  = threadIdx.x;
    int wid  = tid >> 5, lane = tid & 31;
    int wm   = wid & 1;
    int wn   = wid >> 1;
    int rowBase = blockIdx.y * 128;
    int colBase = blockIdx.x * 128;
    int nchunk = K >> 6;

    float acc[4][4][4];
    #pragma unroll
    for (int i = 0; i < 4; i++)
        #pragma unroll
        for (int j = 0; j < 4; j++)
            #pragma unroll
            for (int e = 0; e < 4; e++) acc[i][j][e] = 0.f;

    auto fill = [&](int chunk, int stage) {
        uint32_t sA = stage0 + stage * STAGE_BYTES;
        uint32_t sB = sA + 16384;
        const __half* Ab = A + (size_t)rowBase * K + chunk * 64;
        const __half* Wb = W + (size_t)colBase * K + chunk * 64;
        #pragma unroll
        for (int it = 0; it < 8; it++) {
            int idx = it * 256 + tid;
            int half = idx >> 10;
            int sub  = idx & 1023;
            int r = sub >> 3, c = sub & 7;
            uint32_t off = SWZ(r * 128 + c * 16);
            if (half == 0) cp16(sA + off, Ab + (size_t)r * K + c * 8);
            else           cp16(sB + off, Wb + (size_t)r * K + c * 8);
        }
        CP_COMMIT();
    };

    fill(0, 0);
    fill(1, 1);

    int a_row_off = lane & 15;
    int a_k_off   = (lane >> 4) << 4;
    int b_row_off = (lane & 7) + ((lane >> 4) << 3);
    int b_k_off   = ((lane >> 3) & 1) << 4;

    for (int i = 0; i < nchunk; i++) {
        CP_WAIT1();
        __syncthreads();
        if (i + 2 < nchunk) fill(i + 2, (i + 2) % NST);

        uint32_t sA = stage0 + (i % NST) * STAGE_BYTES;
        uint32_t sB = sA + 16384;
        #pragma unroll
        for (int ks = 0; ks < 4; ks++) {
            int kb = ks * 32;
            uint32_t af[4][4], bf[2][4];
            #pragma unroll
            for (int m = 0; m < 4; m++) {
                int row = wm * 64 + m * 16 + a_row_off;
                ldsm4(af[m], sA + SWZ(row * 128 + kb + a_k_off));
            }
            #pragma unroll
            for (int j = 0; j < 2; j++) {
                int row = wn * 32 + j * 16 + b_row_off;
                ldsm4(bf[j], sB + SWZ(row * 128 + kb + b_k_off));
            }
            #pragma unroll
            for (int m = 0; m < 4; m++)
                #pragma unroll
                for (int n = 0; n < 4; n++)
                    mma16816(acc[m][n], af[m], &bf[n >> 1][(n & 1) * 2]);
        }
        __syncthreads();
    }

    int r0 = rowBase + wm * 64 + (lane >> 2);
    int c0 = colBase + wn * 32 + (lane & 3) * 2;
    #pragma unroll
    for (int m = 0; m < 4; m++) {
        #pragma unroll
        for (int n = 0; n < 4; n++) {
            int col = c0 + n * 8;
            float2 bi = make_float2(0.f, 0.f);
            if (MODE >= 1) bi = *(const float2*)&bias[col];
            #pragma unroll
            for (int hrow = 0; hrow < 2; hrow++) {
                int row = r0 + m * 16 + hrow * 8;
                float v0 = acc[m][n][hrow * 2 + 0];
                float v1 = acc[m][n][hrow * 2 + 1];
                if (MODE >= 1) { v0 += bi.x; v1 += bi.y; }
                if (MODE == 1) {
                    float2 rr = *(const float2*)&resid[(size_t)row * N + col];
                    v0 += rr.x; v1 += rr.y;
                }
                if (MODE == 2) { v0 = gelu_exact(v0); v1 = gelu_exact(v1); }
                if (sizeof(TOUT) == 2) {
                    *(__half2*)((__half*)C + (size_t)row * N + col) =
                        __floats2half2_rn(v0, v1);
                } else {
                    *(float2*)((float*)C + (size_t)row * N + col) =
                        make_float2(v0, v1);
                }
            }
        }
    }
}

// ---------------- HMMA flash attention ----------------
// CTA: 128 threads (4 warps), 64 q-rows. K/V streamed in 64-row tiles,
// double-buffered. smem: Q 8KB | 2 x (K 8KB + V 8KB) | mask 8KB = 48KB.
#define ATTN_SMEM (8192 + 2 * 16384 + 8192)

__global__ void __launch_bounds__(128) attn_mma(
    const __half* __restrict__ q, const __half* __restrict__ k,
    const __half* __restrict__ v, const float* __restrict__ pm,
    __half* __restrict__ out)
{
    extern __shared__ char smraw[];
    uint32_t base = smem_u32(smraw);
    float* Msk = (float*)(smraw + 8192 + 32768);

    int tid = threadIdx.x, wid = tid >> 5, lane = tid & 31;
    int qtile = blockIdx.x, bh = blockIdx.y;
    int b = bh >> 4, h = bh & 15;
    int q0 = qtile * 64;

    const __half* qb = q + ((size_t)b * Sq) * Dm + h * HDm;
    const __half* kb = k + ((size_t)b * Sq) * Dm + h * HDm;
    const __half* vb = v + ((size_t)b * Sq) * Dm + h * HDm;

    // mask -> smem (pre-transformed additive bias)
    {
        const float4* pmb = (const float4*)(pm + (size_t)b * Sq);
        for (int i = tid; i < Sq / 4; i += 128) {
            float4 mv = pmb[i];
            float4 w;
            w.x = (1.f - mv.x) * -10000.f; w.y = (1.f - mv.y) * -10000.f;
            w.z = (1.f - mv.z) * -10000.f; w.w = (1.f - mv.w) * -10000.f;
            ((float4*)Msk)[i] = w;
        }
    }

    // Q tile -> smem (group 0)
    #pragma unroll
    for (int it = 0; it < 4; it++) {
        int idx = it * 128 + tid;
        int r = idx >> 3, c = idx & 7;
        cp16(base + SWZ(r * 128 + c * 16), qb + (size_t)(q0 + r) * Dm + c * 8);
    }
    CP_COMMIT();

    auto fillkv = [&](int kt, int st) {
        uint32_t sK = base + 8192 + st * 16384;
        uint32_t sV = sK + 8192;
        int k0 = kt * 64;
        #pragma unroll
        for (int it = 0; it < 8; it++) {
            int idx = it * 128 + tid;
            int hf = idx >> 9, sub = idx & 511;
            int r = sub >> 3, c = sub & 7;
            uint32_t off = SWZ(r * 128 + c * 16);
            if (hf == 0) cp16(sK + off, kb + (size_t)(k0 + r) * Dm + c * 8);
            else         cp16(sV + off, vb + (size_t)(k0 + r) * Dm + c * 8);
        }
        CP_COMMIT();
    };
    fillkv(0, 0);

    CP_WAIT1();                 // Q tile resident (kv0 may still be in flight)
    __syncthreads();

    int a_row = lane & 15, a_kb = (lane >> 4) << 4;
    int b_row = (lane & 7) + ((lane >> 4) << 3);
    int b_kb  = ((lane >> 3) & 1) << 4;
    int colb  = (lane & 3) * 2;

    uint32_t qf[4][4];
    #pragma unroll
    for (int ks = 0; ks < 4; ks++)
        ldsm4(qf[ks], base + SWZ((wid * 16 + a_row) * 128 + ks * 32 + a_kb));

    float m_[2] = {-1e30f, -1e30f}, l_[2] = {0.f, 0.f};
    float o[8][4];
    #pragma unroll
    for (int nb = 0; nb < 8; nb++)
        #pragma unroll
        for (int e = 0; e < 4; e++) o[nb][e] = 0.f;

    for (int kt = 0; kt < Sq / 64; kt++) {
        int st = kt & 1;
        if (kt + 1 < Sq / 64) { fillkv(kt + 1, st ^ 1); CP_WAIT1(); }
        else                  { CP_WAIT0(); }
        __syncthreads();
        uint32_t sK = base + 8192 + st * 16384;
        uint32_t sV = sK + 8192;
        int k0 = kt * 64;

        // S = Q @ K^T
        float sc[8][4];
        #pragma unroll
        for (int nb = 0; nb < 8; nb++)
            #pragma unroll
            for (int e = 0; e < 4; e++) sc[nb][e] = 0.f;
        #pragma unroll
        for (int np = 0; np < 4; np++) {
            #pragma unroll
            for (int ks = 0; ks < 4; ks++) {
                uint32_t bf[4];
                ldsm4(bf, sK + SWZ((np * 16 + b_row) * 128 + ks * 32 + b_kb));
                mma16816(sc[2 * np],     qf[ks], &bf[0]);
                mma16816(sc[2 * np + 1], qf[ks], &bf[2]);
            }
        }

        // scale + mask + online softmax (fast exp on FMA pipe)
        float ml0 = -1e30f, ml1 = -1e30f;
        #pragma unroll
        for (int nb = 0; nb < 8; nb++) {
            float mk0 = Msk[k0 + nb * 8 + colb];
            float mk1 = Msk[k0 + nb * 8 + colb + 1];
            sc[nb][0] = fmaf(sc[nb][0], 0.125f, mk0);
            sc[nb][1] = fmaf(sc[nb][1], 0.125f, mk1);
            sc[nb][2] = fmaf(sc[nb][2], 0.125f, mk0);
            sc[nb][3] = fmaf(sc[nb][3], 0.125f, mk1);
            ml0 = fmaxf(ml0, fmaxf(sc[nb][0], sc[nb][1]));
            ml1 = fmaxf(ml1, fmaxf(sc[nb][2], sc[nb][3]));
        }
        ml0 = fmaxf(ml0, __shfl_xor_sync(0xffffffffu, ml0, 1));
        ml0 = fmaxf(ml0, __shfl_xor_sync(0xffffffffu, ml0, 2));
        ml1 = fmaxf(ml1, __shfl_xor_sync(0xffffffffu, ml1, 1));
        ml1 = fmaxf(ml1, __shfl_xor_sync(0xffffffffu, ml1, 2));
        float mn0 = fmaxf(m_[0], ml0), mn1 = fmaxf(m_[1], ml1);
        float al0 = fexp2n((m_[0] - mn0) * L2E);
        float al1 = fexp2n((m_[1] - mn1) * L2E);
        float bb0 = mn0 * L2E, bb1 = mn1 * L2E;
        float s0 = 0.f, s1 = 0.f;
        #pragma unroll
        for (int nb = 0; nb < 8; nb++) {
            sc[nb][0] = fexp2n(fmaf(sc[nb][0], L2E, -bb0));
            sc[nb][1] = fexp2n(fmaf(sc[nb][1], L2E, -bb0));
            sc[nb][2] = fexp2n(fmaf(sc[nb][2], L2E, -bb1));
            sc[nb][3] = fexp2n(fmaf(sc[nb][3], L2E, -bb1));
            s0 += sc[nb][0] + sc[nb][1];
            s1 += sc[nb][2] + sc[nb][3];
        }
        s0 += __shfl_xor_sync(0xffffffffu, s0, 1);
        s0 += __shfl_xor_sync(0xffffffffu, s0, 2);
        s1 += __shfl_xor_sync(0xffffffffu, s1, 1);
        s1 += __shfl_xor_sync(0xffffffffu, s1, 2);
        l_[0] = l_[0] * al0 + s0; l_[1] = l_[1] * al1 + s1;
        m_[0] = mn0; m_[1] = mn1;
        #pragma unroll
        for (int nb = 0; nb < 8; nb++) {
            o[nb][0] *= al0; o[nb][1] *= al0;
            o[nb][2] *= al1; o[nb][3] *= al1;
        }

        // O += P @ V  (P stays in registers: S-accum layout == A-frag layout)
        #pragma unroll
        for (int ks = 0; ks < 4; ks++) {
            uint32_t pa[4];
            __half2 p0 = __floats2half2_rn(sc[2*ks][0],   sc[2*ks][1]);
            __half2 p1 = __floats2half2_rn(sc[2*ks][2],   sc[2*ks][3]);
            __half2 p2 = __floats2half2_rn(sc[2*ks+1][0], sc[2*ks+1][1]);
            __half2 p3 = __floats2half2_rn(sc[2*ks+1][2], sc[2*ks+1][3]);
            pa[0] = *(uint32_t*)&p0; pa[1] = *(uint32_t*)&p1;
            pa[2] = *(uint32_t*)&p2; pa[3] = *(uint32_t*)&p3;
            #pragma unroll
            for (int np = 0; np < 4; np++) {
                uint32_t vf[4];
                ldsm4t(vf, sV + SWZ((ks * 16 + a_row) * 128 + np * 32 + a_kb));
                mma16816(o[2 * np],     pa, &vf[0]);
                mma16816(o[2 * np + 1], pa, &vf[2]);
            }
        }
        __syncthreads();
    }

    float inv0 = 1.f / l_[0], inv1 = 1.f / l_[1];
    int r0g = q0 + wid * 16 + (lane >> 2);
    __half* ob = out + ((size_t)b * Sq) * Dm + h * HDm;
    #pragma unroll
    for (int nb = 0; nb < 8; nb++) {
        int col = nb * 8 + colb;
        *(__half2*)&ob[(size_t)r0g * Dm + col] =
            __floats2half2_rn(o[nb][0] * inv0, o[nb][1] * inv0);
        *(__half2*)&ob[(size_t)(r0g + 8) * Dm + col] =
            __floats2half2_rn(o[nb][2] * inv1, o[nb][3] * inv1);
    }
}

// ---------------- launch ----------------
extern "C" void kernel_launch(void* const* d_in, const int* in_sizes, int n_in,
                              void* d_out, int out_size) {
    const float* x     = (const float*)d_in[0];
    const float* pmask = (const float*)d_in[1];
    const float* Wq    = (const float*)d_in[2];
    const float* Wk    = (const float*)d_in[3];
    const float* Wv    = (const float*)d_in[4];
    const float* Wu    = (const float*)d_in[5];
    const float* bu    = (const float*)d_in[6];
    const float* W1    = (const float*)d_in[7];
    const float* b1    = (const float*)d_in[8];
    const float* W2    = (const float*)d_in[9];
    const float* b2    = (const float*)d_in[10];
    const float* g1    = (const float*)d_in[11];
    const float* be1   = (const float*)d_in[12];
    const float* g2    = (const float*)d_in[13];
    const float* be2   = (const float*)d_in[14];
    float* out = (float*)d_out;

    __half *xn16, *q16, *k16, *v16, *ao16, *xm16, *h16;
    __half *wq16, *wk16, *wv16, *wu16, *w116, *w216;
    float *x1;
    cudaGetSymbolAddress((void**)&xn16, g_xn16);
    cudaGetSymbolAddress((void**)&q16,  g_q16);
    cudaGetSymbolAddress((void**)&k16,  g_k16);
    cudaGetSymbolAddress((void**)&v16,  g_v16);
    cudaGetSymbolAddress((void**)&ao16, g_ao16);
    cudaGetSymbolAddress((void**)&x1,   g_x1);
    cudaGetSymbolAddress((void**)&xm16, g_xm16);
    cudaGetSymbolAddress((void**)&h16,  g_h16);
    cudaGetSymbolAddress((void**)&wq16, g_wq16);
    cudaGetSymbolAddress((void**)&wk16, g_wk16);
    cudaGetSymbolAddress((void**)&wv16, g_wv16);
    cudaGetSymbolAddress((void**)&wu16, g_wu16);
    cudaGetSymbolAddress((void**)&w116, g_w116);
    cudaGetSymbolAddress((void**)&w216, g_w216);

    cudaFuncSetAttribute(attn_mma, cudaFuncAttributeMaxDynamicSharedMemorySize,
                         ATTN_SMEM);
    cudaFuncSetAttribute(hgemm_mma<0, __half>,
                         cudaFuncAttributeMaxDynamicSharedMemorySize, GSMEM);
    cudaFuncSetAttribute(hgemm_mma<1, float>,
                         cudaFuncAttributeMaxDynamicSharedMemorySize, GSMEM);
    cudaFuncSetAttribute(hgemm_mma<2, __half>,
                         cudaFuncAttributeMaxDynamicSharedMemorySize, GSMEM);

    // weight conversions
    f2h_kernel<<<Dm * Dm / 1024, 256>>>(Wq, wq16, Dm * Dm);
    f2h_kernel<<<Dm * Dm / 1024, 256>>>(Wk, wk16, Dm * Dm);
    f2h_kernel<<<Dm * Dm / 1024, 256>>>(Wv, wv16, Dm * Dm);
    f2h_kernel<<<Dm * Dm / 1024, 256>>>(Wu, wu16, Dm * Dm);
    f2h_kernel<<<FFm * Dm / 1024, 256>>>(W1, w116, FFm * Dm);
    f2h_kernel<<<Dm * FFm / 1024, 256>>>(W2, w216, Dm * FFm);

    dim3 gD(Dm / 128, ROWS / 128);    // (8, 64)
    dim3 gF(FFm / 128, ROWS / 128);   // (16, 64)

    ln_kernel<<<ROWS, 256>>>(x, g1, be1, xn16);

    hgemm_mma<0, __half><<<gD, 256, GSMEM>>>(xn16, wq16, nullptr, nullptr, q16, ROWS, Dm, Dm);
    hgemm_mma<0, __half><<<gD, 256, GSMEM>>>(xn16, wk16, nullptr, nullptr, k16, ROWS, Dm, Dm);
    hgemm_mma<0, __half><<<gD, 256, GSMEM>>>(xn16, wv16, nullptr, nullptr, v16, ROWS, Dm, Dm);

    attn_mma<<<dim3(Sq / 64, Bsz * Hn), 128, ATTN_SMEM>>>(q16, k16, v16, pmask, ao16);

    hgemm_mma<1, float><<<gD, 256, GSMEM>>>(ao16, wu16, bu, x, x1, ROWS, Dm, Dm);

    ln_kernel<<<ROWS, 256>>>(x1, g2, be2, xm16);

    hgemm_mma<2, __half><<<gF, 256, GSMEM>>>(xm16, w116, b1, nullptr, h16, ROWS, FFm, Dm);

    hgemm_mma<1, float><<<gD, 256, GSMEM>>>(h16, w216, b2, x1, out, ROWS, Dm, FFm);
}